// round 16
// baseline (speedup 1.0000x reference)
#include <cuda_runtime.h>
#include <cuda_fp16.h>
#include <cstdint>

// Problem constants
#define NB     4
#define CIN    512
#define COUT   256
#define DDIM   256
#define SP     16384            // H*W
#define NSPLIT 16
#define SCHUNK (SP / NSPLIT)    // 1024

#define TILE   128
#define T8K    8192             // one split tile: A [128][32] or B [32][128] fp16
#define BUF_B  (4 * T8K)        // A1 A2 B1 B2
#define SMEM3  (3 * BUF_B)      // 98304, triple buffered

// ------------------- global scratch -----------------------------------------
__device__ unsigned short g_f1[(size_t)NB * CIN * SP];    // feat split hi [n][cin][s]
__device__ unsigned short g_f2[(size_t)NB * CIN * SP];    // feat split lo
__device__ unsigned short g_qc1[(size_t)NB * DDIM * SP];  // q split hi [n][d][s]
__device__ unsigned short g_qc2[(size_t)NB * DDIM * SP];  // q split lo
__device__ unsigned short g_k1[(size_t)NB * COUT * SP];   // K split hi [n][c][s]
__device__ unsigned short g_k2[(size_t)NB * COUT * SP];   // K split lo
__device__ unsigned short g_w1s1[COUT * CIN];             // w1 split hi
__device__ unsigned short g_w1s2[COUT * CIN];             // w1 split lo
__device__ unsigned short g_m1[(size_t)NB * COUT * DDIM]; // M split hi [n][o][d]
__device__ unsigned short g_m2[(size_t)NB * COUT * DDIM]; // M split lo
__device__ float g_epart[(size_t)NB * NSPLIT * DDIM * COUT];  // 16 MiB
__device__ float g_att[(size_t)NB * DDIM * COUT];             // 1 MiB

// ---------------- helpers ---------------------------------------------------
__device__ __forceinline__ uint32_t smem_u32(const void* p) {
    uint32_t a;
    asm("{ .reg .u64 t; cvta.to.shared.u64 t, %1; cvt.u32.u64 %0, t; }"
        : "=r"(a) : "l"(p));
    return a;
}
// 64B-row swizzle (A tiles, B non-trans tiles)
__device__ __forceinline__ uint32_t swz64(uint32_t b)  { return b ^ ((b >> 3) & 0x30); }
// 256B-row swizzle (B trans tiles)
__device__ __forceinline__ uint32_t swz256(uint32_t b) { return b ^ ((b >> 4) & 0x70); }

__device__ __forceinline__ void ldsm4(uint32_t* r, uint32_t addr)
{
    asm volatile("ldmatrix.sync.aligned.m8n8.x4.shared.b16 {%0,%1,%2,%3}, [%4];"
                 : "=r"(r[0]), "=r"(r[1]), "=r"(r[2]), "=r"(r[3]) : "r"(addr));
}
__device__ __forceinline__ void ldsm4_t(uint32_t* r, uint32_t addr)
{
    asm volatile("ldmatrix.sync.aligned.m8n8.x4.trans.shared.b16 {%0,%1,%2,%3}, [%4];"
                 : "=r"(r[0]), "=r"(r[1]), "=r"(r[2]), "=r"(r[3]) : "r"(addr));
}
// D += A*B  (m16n8k16, fp16 in, fp32 acc)
__device__ __forceinline__ void mma16816(float* c, const uint32_t* a, const uint32_t* b)
{
    asm volatile(
        "mma.sync.aligned.m16n8k16.row.col.f32.f16.f16.f32 "
        "{%0,%1,%2,%3}, {%4,%5,%6,%7}, {%8,%9}, {%0,%1,%2,%3};"
        : "+f"(c[0]), "+f"(c[1]), "+f"(c[2]), "+f"(c[3])
        : "r"(a[0]), "r"(a[1]), "r"(a[2]), "r"(a[3]), "r"(b[0]), "r"(b[1]));
}
#define CP16(dst, src) asm volatile( \
    "cp.async.cg.shared.global [%0], [%1], 16;" :: "r"(dst), "l"(src) : "memory")
#define CP_COMMIT() asm volatile("cp.async.commit_group;" ::: "memory")
#define CP_WAIT1()  asm volatile("cp.async.wait_group 1;" ::: "memory")

// Split fp32 -> 2 fp16 components (x ~= h1 + h2)
__device__ __forceinline__ void split2(float x, unsigned short& a, unsigned short& b)
{
    __half h1 = __float2half_rn(x);
    float r = x - __half2float(h1);
    __half h2 = __float2half_rn(r);
    a = __half_as_ushort(h1);
    b = __half_as_ushort(h2);
}

// ---------------------------------------------------------------------------
// Elementwise split kernel (coalesced, no transpose)
// ---------------------------------------------------------------------------
__global__ void __launch_bounds__(256) split_clean_k(
    const float4* __restrict__ in, ushort4* __restrict__ o1,
    ushort4* __restrict__ o2, size_t n4)
{
    size_t i = (size_t)blockIdx.x * 256 + threadIdx.x;
    if (i >= n4) return;
    float4 v = in[i];
    unsigned short a1,b1,a2,b2,a3,b3,a4,b4;
    split2(v.x, a1, b1); split2(v.y, a2, b2);
    split2(v.z, a3, b3); split2(v.w, a4, b4);
    o1[i] = make_ushort4(a1, a2, a3, a4);
    o2[i] = make_ushort4(b1, b2, b3, b4);
}

// ---------------------------------------------------------------------------
// Unified tensor-core GEMM. fp16 2-way split, 3 products, all-cp.async,
// 3-stage pipeline (wait_group 1), KC=32.
//   MODE 0 (conv1):  A=w1 splits [o][cin],  B=feat splits [cin][s] TRANS,
//                    epi BN+ReLU -> K splits [c][s]
//   MODE 1 (energy): A=q splits [d][s],     B=K splits [c][s] non-trans,
//                    split-S via z, epi fp32 partials
//   MODE 2 (conv2):  A=M splits [o][d],     B=q splits [d][s] TRANS,
//                    epi +bias -> out
// 128x128 tile, 8 warps (2m x 4n), warp tile 64x32.
// ---------------------------------------------------------------------------
template <int MODE>
__global__ void __launch_bounds__(256, 2) tc2(
    float* __restrict__ outp,
    const float* __restrict__ p0, const float* __restrict__ p1,
    const float* __restrict__ p2, const float* __restrict__ p3)
{
    constexpr bool TRB = (MODE != 1);

    extern __shared__ char sm[];
    const uint32_t smb = smem_u32(sm);
    const int tid = threadIdx.x;
    const int wid = tid >> 5;
    const int lane = tid & 31;
    const int warp_m = wid >> 2;
    const int warp_n = wid & 3;

    const unsigned short *A1, *A2, *B1, *B2;
    float* C = nullptr;
    int lda, ldb, nch;
    size_t kbo = 0;

    if (MODE == 0) {
        const int n = blockIdx.z;
        A1 = g_w1s1; A2 = g_w1s2; lda = CIN;
        const size_t bo = (size_t)n * CIN * SP;
        B1 = g_f1 + bo; B2 = g_f2 + bo; ldb = SP;
        nch = CIN / 32;
        kbo = (size_t)n * COUT * SP;
    } else if (MODE == 1) {
        const int n = blockIdx.z >> 4, sp = blockIdx.z & 15;
        const size_t ao = (size_t)n * DDIM * SP + (size_t)sp * SCHUNK;
        A1 = g_qc1 + ao; A2 = g_qc2 + ao; lda = SP;
        const size_t bo = (size_t)n * COUT * SP + (size_t)sp * SCHUNK;
        B1 = g_k1 + bo; B2 = g_k2 + bo; ldb = SP;
        C = g_epart + (size_t)blockIdx.z * DDIM * COUT;
        nch = SCHUNK / 32;
    } else {
        const int n = blockIdx.z;
        const size_t ao = (size_t)n * COUT * DDIM;
        A1 = g_m1 + ao; A2 = g_m2 + ao; lda = DDIM;
        const size_t bo = (size_t)n * DDIM * SP;
        B1 = g_qc1 + bo; B2 = g_qc2 + bo; ldb = SP;
        C = outp + (size_t)n * COUT * SP;
        nch = DDIM / 32;
    }
    const int tM = blockIdx.y * TILE;
    const int tN = blockIdx.x * TILE;

    // fill thread mappings
    const int fr = tid >> 2;             // A rows (and B non-trans rows)
    const int fc = tid & 3;              // 16B unit within 64B row
    const int br = tid >> 3;             // B trans k-row 0..31
    const int bu = tid & 7;              // B trans 16B unit base

    auto fill = [&](uint32_t buf, int kbase) {
#pragma unroll
        for (int h = 0; h < 2; h++) {
            const int r = fr + h * 64;
            const uint32_t d = swz64((uint32_t)r * 64u + (uint32_t)fc * 16u);
            CP16(buf + d,       A1 + (size_t)(tM + r) * lda + kbase + fc * 8);
            CP16(buf + T8K + d, A2 + (size_t)(tM + r) * lda + kbase + fc * 8);
        }
        if (TRB) {
#pragma unroll
            for (int h = 0; h < 2; h++) {
                const int u = bu + h * 8;
                const uint32_t d = swz256((uint32_t)br * 256u + (uint32_t)u * 16u);
                CP16(buf + 2 * T8K + d, B1 + (size_t)(kbase + br) * ldb + tN + u * 8);
                CP16(buf + 3 * T8K + d, B2 + (size_t)(kbase + br) * ldb + tN + u * 8);
            }
        } else {
#pragma unroll
            for (int h = 0; h < 2; h++) {
                const int r = fr + h * 64;
                const uint32_t d = swz64((uint32_t)r * 64u + (uint32_t)fc * 16u);
                CP16(buf + 2 * T8K + d, B1 + (size_t)(tN + r) * ldb + kbase + fc * 8);
                CP16(buf + 3 * T8K + d, B2 + (size_t)(tN + r) * ldb + kbase + fc * 8);
            }
        }
    };

    float acc[4][4][4];
#pragma unroll
    for (int i = 0; i < 4; i++)
#pragma unroll
        for (int j = 0; j < 4; j++)
#pragma unroll
            for (int v = 0; v < 4; v++) acc[i][j][v] = 0.f;

    // ldmatrix address components
    const int a_row_c = warp_m * 64 + ((tid >> 3) & 1) * 8 + (tid & 7);
    const int a_k_c   = ((tid >> 4) & 1) * 16;   // bytes
    const int b_row_c = warp_n * 32 + ((tid >> 4) & 1) * 8 + (tid & 7);   // non-trans
    const int b_k_c   = ((tid >> 3) & 1) * 16;                            // non-trans
    const int bt_row  = ((tid >> 3) & 1) * 8 + (tid & 7);                 // trans k-row
    const int bt_u    = warp_n * 4 + ((tid >> 4) & 1);                    // trans 16B unit

    const int pa[3] = {0, 0, 1};
    const int pb[3] = {0, 1, 0};

    // 3-stage pipeline prologue: fill buffers 0 and 1
    fill(smb, 0);
    CP_COMMIT();
    fill(smb + BUF_B, 32);
    CP_COMMIT();

    int cur = 0;    // buffer being consumed this iteration
    int nxf = 2;    // buffer to fill this iteration (chunk ch+2)
    for (int ch = 0; ch < nch; ch++) {
        CP_WAIT1();             // chunk ch's fill (2 groups back) has landed
        __syncthreads();        // all warps done with MMA of ch-1 (buffer nxf)
        if (ch + 2 < nch)
            fill(smb + (uint32_t)nxf * BUF_B, (ch + 2) * 32);
        CP_COMMIT();            // exactly one group per iteration (may be empty)

        const uint32_t cb = smb + (uint32_t)cur * BUF_B;
#pragma unroll
        for (int p = 0; p < 3; p++) {
            const uint32_t baseA = cb + (uint32_t)pa[p] * T8K;
            const uint32_t baseB = cb + (uint32_t)(2 + pb[p]) * T8K;
#pragma unroll
            for (int ks = 0; ks < 2; ks++) {
                uint32_t af[4][4];
#pragma unroll
                for (int mf = 0; mf < 4; mf++)
                    ldsm4(af[mf], baseA + swz64((uint32_t)(a_row_c + mf * 16) * 64u
                                                + (uint32_t)(a_k_c + ks * 32)));
                uint32_t bf[2][4];
#pragma unroll
                for (int jj = 0; jj < 2; jj++) {
                    if (TRB) {
                        const uint32_t addr = baseB
                            + swz256((uint32_t)(ks * 16 + bt_row) * 256u
                                     + (uint32_t)(bt_u + jj * 2) * 16u);
                        ldsm4_t(bf[jj], addr);
                    } else {
                        ldsm4(bf[jj], baseB + swz64((uint32_t)(b_row_c + jj * 16) * 64u
                                                    + (uint32_t)(b_k_c + ks * 32)));
                    }
                }
#pragma unroll
                for (int mf = 0; mf < 4; mf++)
#pragma unroll
                    for (int nf = 0; nf < 4; nf++)
                        mma16816(acc[mf][nf], af[mf], &bf[nf >> 1][(nf & 1) * 2]);
            }
        }
        cur = (cur == 2) ? 0 : cur + 1;
        nxf = (nxf == 2) ? 0 : nxf + 1;
    }

    // -------------------- epilogue --------------------
#pragma unroll
    for (int mf = 0; mf < 4; mf++) {
        const int r0 = tM + warp_m * 64 + mf * 16 + (lane >> 2);
        const int r1 = r0 + 8;
        float sc0 = 1.f, sh0 = 0.f, sc1 = 1.f, sh1 = 0.f;
        if (MODE == 0) {
            sc0 = p0[r0] * rsqrtf(p3[r0] + 1e-5f);
            sh0 = p1[r0] - p2[r0] * sc0;
            sc1 = p0[r1] * rsqrtf(p3[r1] + 1e-5f);
            sh1 = p1[r1] - p2[r1] * sc1;
        } else if (MODE == 2) {
            sh0 = p0[r0];
            sh1 = p0[r1];
        }
#pragma unroll
        for (int nf = 0; nf < 4; nf++) {
            const int col = tN + warp_n * 32 + nf * 8 + (lane & 3) * 2;
            float v0 = acc[mf][nf][0], v1 = acc[mf][nf][1];
            float v2 = acc[mf][nf][2], v3 = acc[mf][nf][3];
            if (MODE == 0) {
                v0 = fmaxf(v0 * sc0 + sh0, 0.f);
                v1 = fmaxf(v1 * sc0 + sh0, 0.f);
                v2 = fmaxf(v2 * sc1 + sh1, 0.f);
                v3 = fmaxf(v3 * sc1 + sh1, 0.f);
                unsigned short a1, b1, a2, b2;
                const size_t o0 = kbo + (size_t)r0 * SP + col;
                split2(v0, a1, b1); split2(v1, a2, b2);
                *(uint32_t*)(g_k1 + o0) = (uint32_t)a1 | ((uint32_t)a2 << 16);
                *(uint32_t*)(g_k2 + o0) = (uint32_t)b1 | ((uint32_t)b2 << 16);
                const size_t o1 = kbo + (size_t)r1 * SP + col;
                split2(v2, a1, b1); split2(v3, a2, b2);
                *(uint32_t*)(g_k1 + o1) = (uint32_t)a1 | ((uint32_t)a2 << 16);
                *(uint32_t*)(g_k2 + o1) = (uint32_t)b1 | ((uint32_t)b2 << 16);
            } else if (MODE == 1) {
                *(float2*)(C + (size_t)r0 * COUT + col) = make_float2(v0, v1);
                *(float2*)(C + (size_t)r1 * COUT + col) = make_float2(v2, v3);
            } else {
                v0 += sh0; v1 += sh0; v2 += sh1; v3 += sh1;
                *(float2*)(C + (size_t)r0 * SP + col) = make_float2(v0, v1);
                *(float2*)(C + (size_t)r1 * SP + col) = make_float2(v2, v3);
            }
        }
    }
}

// ---------------------------------------------------------------------------
// Fused split-reduce + softmax: softmax(max-e) == exp(min-e)/sum.
// ---------------------------------------------------------------------------
__global__ void __launch_bounds__(256) softmax_k()
{
    const int nd = blockIdx.x;
    const int n = nd / DDIM;
    const int d = nd % DDIM;
    const int c = threadIdx.x;

    float e = 0.f;
#pragma unroll
    for (int s = 0; s < NSPLIT; s++)
        e += g_epart[((size_t)(n * NSPLIT + s) * DDIM + d) * COUT + c];

    __shared__ float red[256];
    red[c] = e;
    __syncthreads();
    for (int off = 128; off > 0; off >>= 1) {
        if (c < off) red[c] = fminf(red[c], red[c + off]);
        __syncthreads();
    }
    const float emin = red[0];
    __syncthreads();

    const float ex = expf(emin - e);
    red[c] = ex;
    __syncthreads();
    for (int off = 128; off > 0; off >>= 1) {
        if (c < off) red[c] += red[c + off];
        __syncthreads();
    }
    g_att[(size_t)nd * COUT + c] = ex / red[0];
}

// ---------------------------------------------------------------------------
// M[o,d] = sum_c W2[o,c] * att[d,c]; epilogue writes fp16 2-way splits.
// ---------------------------------------------------------------------------
__global__ void __launch_bounds__(256) mmul_k(const float* __restrict__ w2)
{
    const int n = blockIdx.z;
    const float* A = w2;
    const float* B = g_att + (size_t)n * DDIM * COUT;

    const int tI = blockIdx.y * 32;
    const int tJ = blockIdx.x * 32;

    __shared__ float As[32][33];
    __shared__ float Bs[32][33];

    const int tid = threadIdx.x;
    const int r  = tid >> 3;
    const int c4 = (tid & 7) * 4;
    const int io = (tid >> 4) * 2;
    const int jo = (tid & 15) * 2;

    float acc[2][2] = {{0.f, 0.f}, {0.f, 0.f}};

    for (int k0 = 0; k0 < COUT; k0 += 32) {
        float4 av = *(const float4*)(A + (size_t)(tI + r) * COUT + k0 + c4);
        float4 bv = *(const float4*)(B + (size_t)(tJ + r) * COUT + k0 + c4);
        __syncthreads();
        As[c4 + 0][r] = av.x; As[c4 + 1][r] = av.y;
        As[c4 + 2][r] = av.z; As[c4 + 3][r] = av.w;
        Bs[c4 + 0][r] = bv.x; Bs[c4 + 1][r] = bv.y;
        Bs[c4 + 2][r] = bv.z; Bs[c4 + 3][r] = bv.w;
        __syncthreads();
#pragma unroll
        for (int k = 0; k < 32; k++) {
            float a0 = As[k][io], a1 = As[k][io + 1];
            float b0 = Bs[k][jo], b1 = Bs[k][jo + 1];
            acc[0][0] = fmaf(a0, b0, acc[0][0]);
            acc[0][1] = fmaf(a0, b1, acc[0][1]);
            acc[1][0] = fmaf(a1, b0, acc[1][0]);
            acc[1][1] = fmaf(a1, b1, acc[1][1]);
        }
    }
#pragma unroll
    for (int i = 0; i < 2; i++)
#pragma unroll
        for (int j = 0; j < 2; j++) {
            unsigned short a, b;
            split2(acc[i][j], a, b);
            const size_t off = (size_t)n * COUT * DDIM
                             + (size_t)(tI + io + i) * DDIM + tJ + jo + j;
            g_m1[off] = a;
            g_m2[off] = b;
        }
}

// ---------------------------------------------------------------------------
extern "C" void kernel_launch(void* const* d_in, const int* in_sizes, int n_in,
                              void* d_out, int out_size)
{
    const float* feat  = (const float*)d_in[0];
    const float* q     = (const float*)d_in[1];
    const float* w1    = (const float*)d_in[2];
    const float* gamma = (const float*)d_in[3];
    const float* beta  = (const float*)d_in[4];
    const float* mean  = (const float*)d_in[5];
    const float* var   = (const float*)d_in[6];
    const float* w2    = (const float*)d_in[7];
    const float* b2    = (const float*)d_in[8];
    float* out = (float*)d_out;

    void *qc1, *qc2, *w1s1, *w1s2, *f1, *f2;
    cudaGetSymbolAddress(&qc1, g_qc1);   cudaGetSymbolAddress(&qc2, g_qc2);
    cudaGetSymbolAddress(&w1s1, g_w1s1); cudaGetSymbolAddress(&w1s2, g_w1s2);
    cudaGetSymbolAddress(&f1, g_f1);     cudaGetSymbolAddress(&f2, g_f2);

    cudaFuncSetAttribute(tc2<0>, cudaFuncAttributeMaxDynamicSharedMemorySize, SMEM3);
    cudaFuncSetAttribute(tc2<1>, cudaFuncAttributeMaxDynamicSharedMemorySize, SMEM3);
    cudaFuncSetAttribute(tc2<2>, cudaFuncAttributeMaxDynamicSharedMemorySize, SMEM3);

    // 0) elementwise fp16 splits (coalesced, no transpose anywhere)
    {
        size_t n4 = (size_t)NB * DDIM * SP / 4;
        split_clean_k<<<(unsigned)((n4 + 255) / 256), 256>>>(
            (const float4*)q, (ushort4*)qc1, (ushort4*)qc2, n4);
    }
    {
        size_t n4 = (size_t)NB * CIN * SP / 4;
        split_clean_k<<<(unsigned)((n4 + 255) / 256), 256>>>(
            (const float4*)feat, (ushort4*)f1, (ushort4*)f2, n4);
    }
    {
        size_t n4 = (size_t)COUT * CIN / 4;
        split_clean_k<<<(unsigned)((n4 + 255) / 256), 256>>>(
            (const float4*)w1, (ushort4*)w1s1, (ushort4*)w1s2, n4);
    }

    // 1) conv1: K = relu(bn(W1 @ F)) -> K splits
    tc2<0><<<dim3(SP / TILE, COUT / TILE, NB), 256, SMEM3>>>(
        nullptr, gamma, beta, mean, var);

    // 2) energy partials: E[d,c] = Q . K^T, split-S
    tc2<1><<<dim3(COUT / TILE, DDIM / TILE, NB * NSPLIT), 256, SMEM3>>>(
        nullptr, nullptr, nullptr, nullptr, nullptr);

    // 3) reduce + softmax -> attention
    softmax_k<<<NB * DDIM, 256>>>();

    // 4) M = W2 @ att^T -> M splits
    mmul_k<<<dim3(DDIM / 32, COUT / 32, NB), 256>>>(w2);

    // 5) out = M @ Q + b2
    tc2<2><<<dim3(SP / TILE, COUT / TILE, NB), 256, SMEM3>>>(
        out, b2, nullptr, nullptr, nullptr);
}